// round 16
// baseline (speedup 1.0000x reference)
#include <cuda_runtime.h>
#include <math.h>
#include <stdint.h>

#define NN 50000
#define EE 800000
#define HID 100

// ---------------------------------------------------------------------------
// Scratch
// ---------------------------------------------------------------------------
static constexpr size_t SCRATCH_FLOATS =
    6ull * NN * HID + 4ull * NN * 4 + 4096 + 2ull * EE +  // floats
    (4ull * NN + 2) + 2ull * EE + 256;                    // ints (same size)
__device__ float g_scratch[SCRATCH_FLOATS];

// ---------------------------------------------------------------------------
// Small helpers
// ---------------------------------------------------------------------------
__device__ __forceinline__ float elu_f(float v) {
    return (v > 0.f) ? v : (__expf(v) - 1.f);
}

__global__ void k_zero_int(int* __restrict__ p, int n) {
    int i = blockIdx.x * blockDim.x + threadIdx.x;
    if (i < n) p[i] = 0;
}

// ce for both directions: block 0 -> ce[0..3] (AB), block 1 -> ce[4..7] (BA)
__global__ void k_ce2(const float* __restrict__ We0, const float* __restrict__ ae0,
                      const float* __restrict__ We1, const float* __restrict__ ae1,
                      float* __restrict__ ce) {
    const float* We = blockIdx.x ? We1 : We0;
    const float* ae = blockIdx.x ? ae1 : ae0;
    int h = threadIdx.x;
    if (h < 4) {
        float s = 0.f;
        for (int c = 0; c < 25; c++) s += We[h * 25 + c] * ae[h * 25 + c];
        ce[blockIdx.x * 4 + h] = s;
    }
}

// wv[k,h] = sum_c Wd[k, h*25+c] * ad[h*25+c]; 2 directions via blockIdx.x
__global__ void k_wv4_2(const float* __restrict__ Wd0, const float* __restrict__ ad0,
                        float4* __restrict__ wv0,
                        const float* __restrict__ Wd1, const float* __restrict__ ad1,
                        float4* __restrict__ wv1, int K) {
    const float* Wd = blockIdx.x ? Wd1 : Wd0;
    const float* ad = blockIdx.x ? ad1 : ad0;
    float4* wv = blockIdx.x ? wv1 : wv0;
    int k = threadIdx.x;
    if (k >= K) return;
    float o[4];
#pragma unroll
    for (int h = 0; h < 4; h++) {
        float s = 0.f;
        for (int c = 0; c < 25; c++)
            s += Wd[(size_t)k * 100 + h * 25 + c] * ad[h * 25 + c];
        o[h] = s;
    }
    wv[k] = make_float4(o[0], o[1], o[2], o[3]);
}

__global__ void k_wv1_2(const float* __restrict__ Wd0, const float* __restrict__ ad0,
                        float* __restrict__ wv0,
                        const float* __restrict__ Wd1, const float* __restrict__ ad1,
                        float* __restrict__ wv1, int K) {
    const float* Wd = blockIdx.x ? Wd1 : Wd0;
    const float* ad = blockIdx.x ? ad1 : ad0;
    float* wv = blockIdx.x ? wv1 : wv0;
    int k = threadIdx.x;
    if (k >= K) return;
    float s = 0.f;
    for (int c = 0; c < 100; c++) s += Wd[(size_t)k * 100 + c] * ad[c];
    wv[k] = s;
}

// ---------------------------------------------------------------------------
// Combined CSR build over both directions (dir1 nodes offset by NN,
// dir1 edge slots naturally land in [EE, 2EE) of the concatenated arrays).
// ---------------------------------------------------------------------------
__global__ void k_hist2(const int* __restrict__ dAB, const int* __restrict__ dBA,
                        int* __restrict__ cnt) {
    int e = blockIdx.x * blockDim.x + threadIdx.x;
    if (e < EE) atomicAdd(&cnt[dAB[e]], 1);
    else if (e < 2 * EE) atomicAdd(&cnt[dBA[e - EE] + NN], 1);
}

// exclusive scan over n ints; writes rowptr AND cursor (scatter state).
__global__ void k_scan(const int* __restrict__ cnt, int* __restrict__ rowptr,
                       int* __restrict__ cursor, int n) {
    __shared__ int sh_carry;
    __shared__ int wsum[32];
    int t = threadIdx.x, lane = t & 31, w = t >> 5;
    if (t == 0) sh_carry = 0;
    __syncthreads();
    for (int base = 0; base < n; base += 1024) {
        int v = (base + t < n) ? cnt[base + t] : 0;
        int x = v;
#pragma unroll
        for (int o = 1; o < 32; o <<= 1) {
            int y = __shfl_up_sync(0xffffffffu, x, o);
            if (lane >= o) x += y;
        }
        if (lane == 31) wsum[w] = x;
        __syncthreads();
        if (w == 0) {
            int s = wsum[lane];
#pragma unroll
            for (int o = 1; o < 32; o <<= 1) {
                int y = __shfl_up_sync(0xffffffffu, s, o);
                if (lane >= o) s += y;
            }
            wsum[lane] = s;
        }
        __syncthreads();
        int incl = x + ((w > 0) ? wsum[w - 1] : 0);
        int excl = incl - v + sh_carry;
        if (base + t < n) { rowptr[base + t] = excl; cursor[base + t] = excl; }
        __syncthreads();
        if (t == 0) sh_carry += wsum[31];
        __syncthreads();
    }
    if (threadIdx.x == 0) rowptr[n] = sh_carry;
}

__global__ void k_scatter2(const int* __restrict__ sAB, const int* __restrict__ dAB,
                           const float* __restrict__ wAB,
                           const int* __restrict__ sBA, const int* __restrict__ dBA,
                           const float* __restrict__ wBA,
                           int* __restrict__ cursor,
                           int* __restrict__ src_s, float* __restrict__ ew_s) {
    int e = blockIdx.x * blockDim.x + threadIdx.x;
    int node, sv; float wv;
    if (e < EE)            { node = dAB[e];           sv = sAB[e];      wv = wAB[e]; }
    else if (e < 2 * EE)   { node = dBA[e - EE] + NN; sv = sBA[e - EE]; wv = wBA[e - EE]; }
    else return;
    int pos = atomicAdd(&cursor[node], 1);
    src_s[pos] = sv;
    ew_s[pos] = wv;
}

// ---------------------------------------------------------------------------
// Fused GEMM + attention-dot, BOTH directions in one launch.
// blocks [0, half) -> dir0, [half, 2*half) -> dir1.
// ---------------------------------------------------------------------------
template <int K, int HEADS, bool ELU>
__global__ __launch_bounds__(128)
void k_gemm2(const float* __restrict__ X0, const float* __restrict__ W0,
             const float* __restrict__ a0, float* __restrict__ H0, float* __restrict__ att0,
             const float* __restrict__ X1, const float* __restrict__ W1,
             const float* __restrict__ a1, float* __restrict__ H1, float* __restrict__ att1,
             int N) {
    extern __shared__ float sh[];
    float* Ws = sh;            // K*100 floats
    float* xs = sh + K * 100;  // 32*K floats

    const int half = gridDim.x >> 1;
    const int dir = (blockIdx.x >= half) ? 1 : 0;
    const int bid = blockIdx.x - dir * half;
    const float* X = dir ? X1 : X0;
    const float* W = dir ? W1 : W0;
    const float* avec = dir ? a1 : a0;
    float* H = dir ? H1 : H0;
    float* att = dir ? att1 : att0;

    const int t = threadIdx.x;
    const int lane = t & 31;
    const int w = t >> 5;
    const int KW = K / 4;

    {
        const float4* W4 = (const float4*)W;
        float4* Ws4 = (float4*)Ws;
        for (int i = t; i < K * 25; i += 128) Ws4[i] = W4[i];
    }

    float4 av = make_float4(0.f, 0.f, 0.f, 0.f);
    if (lane < 25) av = ((const float4*)avec)[lane];

    for (int g0 = bid * 32; g0 < N; g0 += half * 32) {
        __syncthreads();
        {
            const float4* X4 = (const float4*)X;
            float4* xs4 = (float4*)xs;
            for (int i = t; i < 32 * KW; i += 128) {
                int r = i / KW, c = i - r * KW;
                float4 v = make_float4(0.f, 0.f, 0.f, 0.f);
                if (g0 + r < N) v = X4[(size_t)(g0 + r) * KW + c];
                if (ELU) {
                    v.x = elu_f(v.x); v.y = elu_f(v.y);
                    v.z = elu_f(v.z); v.w = elu_f(v.w);
                }
                xs4[i] = v;
            }
        }
        __syncthreads();

        float acc[8][4];
#pragma unroll
        for (int r = 0; r < 8; r++)
#pragma unroll
            for (int j = 0; j < 4; j++) acc[r][j] = 0.f;

        if (lane < 25) {
            const float4* Ws4 = (const float4*)Ws;
            const float4* xr = (const float4*)(xs + w * 8 * K);
#pragma unroll 2
            for (int k4 = 0; k4 < KW; k4++) {
                float4 w0 = Ws4[(4 * k4 + 0) * 25 + lane];
                float4 w1 = Ws4[(4 * k4 + 1) * 25 + lane];
                float4 w2 = Ws4[(4 * k4 + 2) * 25 + lane];
                float4 w3 = Ws4[(4 * k4 + 3) * 25 + lane];
#pragma unroll
                for (int r = 0; r < 8; r++) {
                    float4 xv = xr[r * KW + k4];
                    acc[r][0] += xv.x * w0.x; acc[r][1] += xv.x * w0.y;
                    acc[r][2] += xv.x * w0.z; acc[r][3] += xv.x * w0.w;
                    acc[r][0] += xv.y * w1.x; acc[r][1] += xv.y * w1.y;
                    acc[r][2] += xv.y * w1.z; acc[r][3] += xv.y * w1.w;
                    acc[r][0] += xv.z * w2.x; acc[r][1] += xv.z * w2.y;
                    acc[r][2] += xv.z * w2.z; acc[r][3] += xv.z * w2.w;
                    acc[r][0] += xv.w * w3.x; acc[r][1] += xv.w * w3.y;
                    acc[r][2] += xv.w * w3.z; acc[r][3] += xv.w * w3.w;
                }
            }
        }

#pragma unroll
        for (int r = 0; r < 8; r++) {
            int n = g0 + w * 8 + r;
            bool ok = (n < N);
            if (ok && lane < 25) {
                float4 hv = make_float4(acc[r][0], acc[r][1], acc[r][2], acc[r][3]);
                ((float4*)(H + (size_t)n * 100))[lane] = hv;
            }
            if (HEADS == 1) {
                float s = acc[r][0] * av.x + acc[r][1] * av.y +
                          acc[r][2] * av.z + acc[r][3] * av.w;
#pragma unroll
                for (int o = 16; o > 0; o >>= 1)
                    s += __shfl_xor_sync(0xffffffffu, s, o);
                if (ok && lane == 0) att[n] = s;
            } else {
                float s0 = 0.f, s1 = 0.f, s2 = 0.f, s3 = 0.f;
#pragma unroll
                for (int j = 0; j < 4; j++) {
                    int c = 4 * lane + j;
                    float a = (j == 0) ? av.x : (j == 1) ? av.y
                              : (j == 2) ? av.z : av.w;
                    float v = acc[r][j] * a;
                    int h = c / 25;
                    if (h == 0) s0 += v;
                    else if (h == 1) s1 += v;
                    else if (h == 2) s2 += v;
                    else s3 += v;
                }
#pragma unroll
                for (int o = 16; o > 0; o >>= 1) {
                    s0 += __shfl_xor_sync(0xffffffffu, s0, o);
                    s1 += __shfl_xor_sync(0xffffffffu, s1, o);
                    s2 += __shfl_xor_sync(0xffffffffu, s2, o);
                    s3 += __shfl_xor_sync(0xffffffffu, s3, o);
                }
                if (ok && lane == 0) {
                    float* ap = att + (size_t)n * 4;
                    ap[0] = s0; ap[1] = s1; ap[2] = s2; ap[3] = s3;
                }
            }
        }
    }
}

// ---------------------------------------------------------------------------
// GEMV both directions: att[n,h] = sum_k X[n,k] * wv[k,h].  Warp per node.
// ---------------------------------------------------------------------------
__global__ __launch_bounds__(256)
void k_gemv4_2(const float* __restrict__ X0, const float4* __restrict__ wvA,
               float* __restrict__ att0,
               const float* __restrict__ X1, const float4* __restrict__ wvB,
               float* __restrict__ att1, int N) {
    int lane = threadIdx.x & 31;
    int wid = (blockIdx.x * blockDim.x + threadIdx.x) >> 5;
    if (wid >= 2 * N) return;
    int dir = (wid >= N) ? 1 : 0;
    int n = wid - dir * N;
    const float* X = dir ? X1 : X0;
    const float4* wv = dir ? wvB : wvA;
    float* att = dir ? att1 : att0;
    float4 w0 = wv[4 * lane + 0];
    float4 w1 = wv[4 * lane + 1];
    float4 w2 = wv[4 * lane + 2];
    float4 w3 = wv[4 * lane + 3];
    float4 xv = ((const float4*)X)[(size_t)n * 32 + lane];
    float s0 = xv.x * w0.x + xv.y * w1.x + xv.z * w2.x + xv.w * w3.x;
    float s1 = xv.x * w0.y + xv.y * w1.y + xv.z * w2.y + xv.w * w3.y;
    float s2 = xv.x * w0.z + xv.y * w1.z + xv.z * w2.z + xv.w * w3.z;
    float s3 = xv.x * w0.w + xv.y * w1.w + xv.z * w2.w + xv.w * w3.w;
#pragma unroll
    for (int o = 16; o > 0; o >>= 1) {
        s0 += __shfl_xor_sync(0xffffffffu, s0, o);
        s1 += __shfl_xor_sync(0xffffffffu, s1, o);
        s2 += __shfl_xor_sync(0xffffffffu, s2, o);
        s3 += __shfl_xor_sync(0xffffffffu, s3, o);
    }
    if (lane == 0) ((float4*)att)[n] = make_float4(s0, s1, s2, s3);
}

__global__ __launch_bounds__(256)
void k_gemv1_2(const float* __restrict__ X0, const float* __restrict__ wvA,
               float* __restrict__ att0,
               const float* __restrict__ X1, const float* __restrict__ wvB,
               float* __restrict__ att1, int N) {
    int lane = threadIdx.x & 31;
    int wid = (blockIdx.x * blockDim.x + threadIdx.x) >> 5;
    if (wid >= 2 * N) return;
    int dir = (wid >= N) ? 1 : 0;
    int n = wid - dir * N;
    const float* X = dir ? X1 : X0;
    const float* wv = dir ? wvB : wvA;
    float* att = dir ? att1 : att0;
    float s = 0.f;
    if (lane < 25) {
        float4 wvv = ((const float4*)wv)[lane];
        float4 xv = ((const float4*)X)[(size_t)n * 25 + lane];
        s = elu_f(xv.x) * wvv.x + elu_f(xv.y) * wvv.y +
            elu_f(xv.z) * wvv.z + elu_f(xv.w) * wvv.w;
    }
#pragma unroll
    for (int o = 16; o > 0; o >>= 1) s += __shfl_xor_sync(0xffffffffu, s, o);
    if (lane == 0) att[n] = s;
}

// ---------------------------------------------------------------------------
// Fused GAT gather, both directions, warp per destination node.
// 1-deep software pipeline over the edge list to hide the src->hs[src] chain.
// ---------------------------------------------------------------------------
template <int HEADS>
__global__ __launch_bounds__(256)
void k_gat2(const int* __restrict__ rowptr, const int* __restrict__ srcs,
            const float* __restrict__ ews, const float* __restrict__ ce,
            const float* __restrict__ atts0, const float* __restrict__ attd0,
            const float* __restrict__ hsrc0, const float* __restrict__ b0,
            float* __restrict__ out0,
            const float* __restrict__ atts1, const float* __restrict__ attd1,
            const float* __restrict__ hsrc1, const float* __restrict__ b1,
            float* __restrict__ out1, int n) {
    int wid = (blockIdx.x * blockDim.x + threadIdx.x) >> 5;
    int lane = threadIdx.x & 31;
    if (wid >= 2 * n) return;
    int dir = (wid >= n) ? 1 : 0;
    int node = wid - dir * n;
    const float* atts = dir ? atts1 : atts0;
    const float* attd = dir ? attd1 : attd0;
    const float4* hs4 = (const float4*)(dir ? hsrc1 : hsrc0);
    const float4* b4 = (const float4*)(dir ? b1 : b0);
    float* out = dir ? out1 : out0;

    int beg = rowptr[wid], end = rowptr[wid + 1];
    if (end == beg) {
        if (lane < 25) ((float4*)out)[(size_t)node * 25 + lane] = b4[lane];
        return;
    }
    float4 acc = make_float4(0.f, 0.f, 0.f, 0.f);
    if (HEADS == 4) {
        int c0 = 4 * lane;
        int h0 = c0 / 25, h1 = (c0 + 1) / 25, h2 = (c0 + 2) / 25, h3 = (c0 + 3) / 25;
        float ad_l = 0.f, ce_l = 0.f;
        if (lane < 4) {
            ad_l = attd[(size_t)node * 4 + lane];
            ce_l = ce[dir * 4 + lane];
        }
        float dn = 0.f;
        // prefetch stage
        int sN = srcs[beg];
        float wN = ews[beg];
        float atN = (lane < 4) ? atts[(size_t)sN * 4 + lane] : 0.f;
        float4 hvN = make_float4(0.f, 0.f, 0.f, 0.f);
        if (lane < 25) hvN = hs4[(size_t)sN * 25 + lane];
        for (int i = beg; i < end; i++) {
            float w_ = wN, at_ = atN;
            float4 hv = hvN;
            if (i + 1 < end) {
                sN = srcs[i + 1];
                wN = ews[i + 1];
                if (lane < 4) atN = atts[(size_t)sN * 4 + lane];
                if (lane < 25) hvN = hs4[(size_t)sN * 25 + lane];
            }
            float v = 0.f;
            if (lane < 4) {
                float l = at_ + ad_l + w_ * ce_l;
                l = (l > 0.f) ? l : 0.2f * l;
                v = __expf(l);
                dn += v;
            }
            float a0 = __shfl_sync(0xffffffffu, v, h0);
            float a1 = __shfl_sync(0xffffffffu, v, h1);
            float a2 = __shfl_sync(0xffffffffu, v, h2);
            float a3 = __shfl_sync(0xffffffffu, v, h3);
            if (lane < 25) {
                acc.x += a0 * hv.x; acc.y += a1 * hv.y;
                acc.z += a2 * hv.z; acc.w += a3 * hv.w;
            }
        }
        float r0 = __shfl_sync(0xffffffffu, dn, h0);
        float r1 = __shfl_sync(0xffffffffu, dn, h1);
        float r2 = __shfl_sync(0xffffffffu, dn, h2);
        float r3 = __shfl_sync(0xffffffffu, dn, h3);
        if (lane < 25) {
            float4 bv = b4[lane];
            float4 o;
            o.x = bv.x + __fdividef(acc.x, r0);
            o.y = bv.y + __fdividef(acc.y, r1);
            o.z = bv.z + __fdividef(acc.z, r2);
            o.w = bv.w + __fdividef(acc.w, r3);
            ((float4*)out)[(size_t)node * 25 + lane] = o;
        }
    } else {
        float ad = attd[node];
        float dn = 0.f;
        int sN = srcs[beg];
        float atN = (lane == 0) ? atts[sN] : 0.f;
        float4 hvN = make_float4(0.f, 0.f, 0.f, 0.f);
        if (lane < 25) hvN = hs4[(size_t)sN * 25 + lane];
        for (int i = beg; i < end; i++) {
            float at_ = atN;
            float4 hv = hvN;
            if (i + 1 < end) {
                sN = srcs[i + 1];
                if (lane == 0) atN = atts[sN];
                if (lane < 25) hvN = hs4[(size_t)sN * 25 + lane];
            }
            float v = 0.f;
            if (lane == 0) {
                float l = at_ + ad;
                l = (l > 0.f) ? l : 0.2f * l;
                v = __expf(l);
                dn += v;
            }
            float a = __shfl_sync(0xffffffffu, v, 0);
            if (lane < 25) {
                acc.x += a * hv.x; acc.y += a * hv.y;
                acc.z += a * hv.z; acc.w += a * hv.w;
            }
        }
        float r = __shfl_sync(0xffffffffu, dn, 0);
        if (lane < 25) {
            float4 bv = b4[lane];
            float rr = __fdividef(1.f, r);
            float4 o;
            o.x = bv.x + acc.x * rr; o.y = bv.y + acc.y * rr;
            o.z = bv.z + acc.z * rr; o.w = bv.w + acc.w * rr;
            ((float4*)out)[(size_t)node * 25 + lane] = o;
        }
    }
}

// ---------------------------------------------------------------------------
// Host orchestration
// ---------------------------------------------------------------------------
extern "C" void kernel_launch(void* const* d_in, const int* in_sizes, int n_in,
                              void* d_out, int out_size) {
    (void)in_sizes; (void)n_in; (void)out_size;

    const float* x_A  = (const float*)d_in[0];
    const float* x_B  = (const float*)d_in[1];
    const int*   eiAB = (const int*)d_in[2];
    const int*   eiBA = (const int*)d_in[3];
    const float* w_AB = (const float*)d_in[4];
    const float* w_BA = (const float*)d_in[5];
    const float* l1ABWs = (const float*)d_in[6];
    const float* l1ABWd = (const float*)d_in[7];
    const float* l1ABas = (const float*)d_in[8];
    const float* l1ABad = (const float*)d_in[9];
    const float* l1ABWe = (const float*)d_in[10];
    const float* l1ABae = (const float*)d_in[11];
    const float* l1ABb  = (const float*)d_in[12];
    const float* l2ABWs = (const float*)d_in[13];
    const float* l2ABWd = (const float*)d_in[14];
    const float* l2ABas = (const float*)d_in[15];
    const float* l2ABad = (const float*)d_in[16];
    const float* l2ABb  = (const float*)d_in[17];
    const float* l1BAWs = (const float*)d_in[18];
    const float* l1BAWd = (const float*)d_in[19];
    const float* l1BAas = (const float*)d_in[20];
    const float* l1BAad = (const float*)d_in[21];
    const float* l1BAWe = (const float*)d_in[22];
    const float* l1BAae = (const float*)d_in[23];
    const float* l1BAb  = (const float*)d_in[24];
    const float* l2BAWs = (const float*)d_in[25];
    const float* l2BAWd = (const float*)d_in[26];
    const float* l2BAas = (const float*)d_in[27];
    const float* l2BAad = (const float*)d_in[28];
    const float* l2BAb  = (const float*)d_in[29];

    const int* sAB = eiAB;        const int* dAB = eiAB + EE;
    const int* sBA = eiBA;        const int* dBA = eiBA + EE;

    void* sp = nullptr;
    cudaGetSymbolAddress(&sp, g_scratch);
    float* p = (float*)sp;
    float* hsA  = p; p += (size_t)NN * HID;   // x_A @ l1_AB_Ws
    float* hsB  = p; p += (size_t)NN * HID;   // x_B @ l1_BA_Ws
    float* hA   = p; p += (size_t)NN * HID;   // layer-1 output A (incl bias)
    float* hB   = p; p += (size_t)NN * HID;   // layer-1 output B (incl bias)
    float* hs2A = p; p += (size_t)NN * HID;   // elu(hA) @ l2_AB_Ws
    float* hs2B = p; p += (size_t)NN * HID;   // elu(hB) @ l2_BA_Ws
    float* asAB = p; p += (size_t)NN * 4;
    float* adAB = p; p += (size_t)NN * 4;
    float* asBA = p; p += (size_t)NN * 4;
    float* adBA = p; p += (size_t)NN * 4;
    float* ce   = p; p += 16;
    float* wv1AB = p; p += 512;
    float* wv1BA = p; p += 512;
    float* wv2AB = p; p += 128;
    float* wv2BA = p; p += 128;
    p += 752;                                  // pad to 16B multiples
    float* ew_s = p; p += 2ull * EE;           // dst-sorted edge weights (both)
    int* ip = (int*)p;
    int* rowptr = ip; ip += 2 * NN + 1;
    int* cursor = ip; ip += 2 * NN;
    ip += 3;                                   // align
    int* src_s = ip; ip += 2 * EE;             // dst-sorted src ids (both)

    float* oA = (float*)d_out;
    float* oB = oA + (size_t)NN * HID;

    cudaFuncSetAttribute((const void*)k_gemm2<128, 4, false>,
                         cudaFuncAttributeMaxDynamicSharedMemorySize, 69632);
    cudaFuncSetAttribute((const void*)k_gemm2<100, 1, true>,
                         cudaFuncAttributeMaxDynamicSharedMemorySize, 61440);

    const int GRID_GEMM2 = 888;                 // 444 per direction
    const size_t SM128 = (128 * 100 + 32 * 128) * sizeof(float);
    const size_t SM100 = (100 * 100 + 32 * 100) * sizeof(float);
    const int EB2 = (2 * EE + 255) / 256;
    const int NB2 = (2 * NN + 255) / 256;
    const int WARP2_BLOCKS = (2 * NN * 32 + 255) / 256;  // warp/node, both dirs

    // ---------------- CSR build (once; both directions) ------------------
    k_zero_int<<<NB2, 256>>>(cursor, 2 * NN);
    k_hist2<<<EB2, 256>>>(dAB, dBA, cursor);
    k_scan<<<1, 1024>>>(cursor, rowptr, cursor, 2 * NN);
    k_scatter2<<<EB2, 256>>>(sAB, dAB, w_AB, sBA, dBA, w_BA, cursor, src_s, ew_s);

    k_ce2<<<2, 32>>>(l1ABWe, l1ABae, l1BAWe, l1BAae, ce);
    k_wv4_2<<<2, 128>>>(l1ABWd, l1ABad, (float4*)wv1AB,
                        l1BAWd, l1BAad, (float4*)wv1BA, 128);

    // ---------------- Layer 1 (heads=4, edge term) -----------------------
    k_gemm2<128, 4, false><<<GRID_GEMM2, 128, SM128>>>(
        x_A, l1ABWs, l1ABas, hsA, asAB,
        x_B, l1BAWs, l1BAas, hsB, asBA, NN);
    k_gemv4_2<<<WARP2_BLOCKS, 256>>>(x_B, (const float4*)wv1AB, adAB,
                                     x_A, (const float4*)wv1BA, adBA, NN);

    k_gat2<4><<<WARP2_BLOCKS, 256>>>(rowptr, src_s, ew_s, ce,
                                     asAB, adAB, hsA, l1ABb, hB,
                                     asBA, adBA, hsB, l1BAb, hA, NN);

    // ---------------- Layer 2 (heads=1, ELU fused) -----------------------
    k_wv1_2<<<2, 128>>>(l2ABWd, l2ABad, wv2AB, l2BAWd, l2BAad, wv2BA, 100);

    k_gemm2<100, 1, true><<<GRID_GEMM2, 128, SM100>>>(
        hA, l2ABWs, l2ABas, hs2A, asAB,
        hB, l2BAWs, l2BAas, hs2B, asBA, NN);
    k_gemv1_2<<<WARP2_BLOCKS, 256>>>(hB, wv2AB, adAB, hA, wv2BA, adBA, NN);

    k_gat2<1><<<WARP2_BLOCKS, 256>>>(rowptr, src_s, nullptr, nullptr,
                                     asAB, adAB, hs2A, l2ABb, oB,
                                     asBA, adBA, hs2B, l2BAb, oA, NN);
}

// round 17
// speedup vs baseline: 1.1088x; 1.1088x over previous
#include <cuda_runtime.h>
#include <math.h>
#include <stdint.h>

#define NN 50000
#define EE 800000
#define HID 100

// ---------------------------------------------------------------------------
// Scratch
// ---------------------------------------------------------------------------
static constexpr size_t SCRATCH_FLOATS =
    6ull * NN * HID + 4ull * NN * 4 + 4096 + 2ull * EE +  // floats
    (4ull * NN + 2) + 2ull * EE + 256;                    // ints (same size)
__device__ float g_scratch[SCRATCH_FLOATS];

// ---------------------------------------------------------------------------
// Small helpers
// ---------------------------------------------------------------------------
__device__ __forceinline__ float elu_f(float v) {
    return (v > 0.f) ? v : (__expf(v) - 1.f);
}

__global__ void k_zero_int(int* __restrict__ p, int n) {
    int i = blockIdx.x * blockDim.x + threadIdx.x;
    if (i < n) p[i] = 0;
}

// ce for both directions: block 0 -> ce[0..3] (AB), block 1 -> ce[4..7] (BA)
__global__ void k_ce2(const float* __restrict__ We0, const float* __restrict__ ae0,
                      const float* __restrict__ We1, const float* __restrict__ ae1,
                      float* __restrict__ ce) {
    const float* We = blockIdx.x ? We1 : We0;
    const float* ae = blockIdx.x ? ae1 : ae0;
    int h = threadIdx.x;
    if (h < 4) {
        float s = 0.f;
        for (int c = 0; c < 25; c++) s += We[h * 25 + c] * ae[h * 25 + c];
        ce[blockIdx.x * 4 + h] = s;
    }
}

// wv[k,h] = sum_c Wd[k, h*25+c] * ad[h*25+c]; 2 directions via blockIdx.x
__global__ void k_wv4_2(const float* __restrict__ Wd0, const float* __restrict__ ad0,
                        float4* __restrict__ wv0,
                        const float* __restrict__ Wd1, const float* __restrict__ ad1,
                        float4* __restrict__ wv1, int K) {
    const float* Wd = blockIdx.x ? Wd1 : Wd0;
    const float* ad = blockIdx.x ? ad1 : ad0;
    float4* wv = blockIdx.x ? wv1 : wv0;
    int k = threadIdx.x;
    if (k >= K) return;
    float o[4];
#pragma unroll
    for (int h = 0; h < 4; h++) {
        float s = 0.f;
        for (int c = 0; c < 25; c++)
            s += Wd[(size_t)k * 100 + h * 25 + c] * ad[h * 25 + c];
        o[h] = s;
    }
    wv[k] = make_float4(o[0], o[1], o[2], o[3]);
}

__global__ void k_wv1_2(const float* __restrict__ Wd0, const float* __restrict__ ad0,
                        float* __restrict__ wv0,
                        const float* __restrict__ Wd1, const float* __restrict__ ad1,
                        float* __restrict__ wv1, int K) {
    const float* Wd = blockIdx.x ? Wd1 : Wd0;
    const float* ad = blockIdx.x ? ad1 : ad0;
    float* wv = blockIdx.x ? wv1 : wv0;
    int k = threadIdx.x;
    if (k >= K) return;
    float s = 0.f;
    for (int c = 0; c < 100; c++) s += Wd[(size_t)k * 100 + c] * ad[c];
    wv[k] = s;
}

// ---------------------------------------------------------------------------
// Combined CSR build over both directions (dir1 nodes offset by NN,
// dir1 edge slots land in [EE, 2EE) of the concatenated arrays).
// ---------------------------------------------------------------------------
__global__ void k_hist2(const int* __restrict__ dAB, const int* __restrict__ dBA,
                        int* __restrict__ cnt) {
    int e = blockIdx.x * blockDim.x + threadIdx.x;
    if (e < EE) atomicAdd(&cnt[dAB[e]], 1);
    else if (e < 2 * EE) atomicAdd(&cnt[dBA[e - EE] + NN], 1);
}

// exclusive scan over n ints; writes rowptr AND cursor (scatter state).
__global__ void k_scan(const int* __restrict__ cnt, int* __restrict__ rowptr,
                       int* __restrict__ cursor, int n) {
    __shared__ int sh_carry;
    __shared__ int wsum[32];
    int t = threadIdx.x, lane = t & 31, w = t >> 5;
    if (t == 0) sh_carry = 0;
    __syncthreads();
    for (int base = 0; base < n; base += 1024) {
        int v = (base + t < n) ? cnt[base + t] : 0;
        int x = v;
#pragma unroll
        for (int o = 1; o < 32; o <<= 1) {
            int y = __shfl_up_sync(0xffffffffu, x, o);
            if (lane >= o) x += y;
        }
        if (lane == 31) wsum[w] = x;
        __syncthreads();
        if (w == 0) {
            int s = wsum[lane];
#pragma unroll
            for (int o = 1; o < 32; o <<= 1) {
                int y = __shfl_up_sync(0xffffffffu, s, o);
                if (lane >= o) s += y;
            }
            wsum[lane] = s;
        }
        __syncthreads();
        int incl = x + ((w > 0) ? wsum[w - 1] : 0);
        int excl = incl - v + sh_carry;
        if (base + t < n) { rowptr[base + t] = excl; cursor[base + t] = excl; }
        __syncthreads();
        if (t == 0) sh_carry += wsum[31];
        __syncthreads();
    }
    if (threadIdx.x == 0) rowptr[n] = sh_carry;
}

__global__ void k_scatter2(const int* __restrict__ sAB, const int* __restrict__ dAB,
                           const float* __restrict__ wAB,
                           const int* __restrict__ sBA, const int* __restrict__ dBA,
                           const float* __restrict__ wBA,
                           int* __restrict__ cursor,
                           int* __restrict__ src_s, float* __restrict__ ew_s) {
    int e = blockIdx.x * blockDim.x + threadIdx.x;
    int node, sv; float wv;
    if (e < EE)            { node = dAB[e];           sv = sAB[e];      wv = wAB[e]; }
    else if (e < 2 * EE)   { node = dBA[e - EE] + NN; sv = sBA[e - EE]; wv = wBA[e - EE]; }
    else return;
    int pos = atomicAdd(&cursor[node], 1);
    src_s[pos] = sv;
    ew_s[pos] = wv;
}

// ---------------------------------------------------------------------------
// Fused GEMM + attention-dot with register double-buffering of the X tile.
// H[n,:] = X[n,:] @ W ; att[n,h] = <H-row, a_h>
// Block 128 thr (4 warps), 8 rows/warp -> 32 rows/iter, k-vectorized x4.
// Next tile is prefetched into registers while the current tile computes,
// hiding the ~600-cycle LDG latency behind the FFMA phase.
// ---------------------------------------------------------------------------
template <int K, int HEADS, bool ELU>
__global__ __launch_bounds__(128)
void k_gemm_att(const float* __restrict__ X, const float* __restrict__ W,
                const float* __restrict__ avec, float* __restrict__ H,
                float* __restrict__ att, int N) {
    extern __shared__ float sh[];
    float* Ws = sh;            // K*100 floats
    float* xs = sh + K * 100;  // 32*K floats

    const int t = threadIdx.x;
    const int lane = t & 31;
    const int w = t >> 5;
    const int KW = K / 4;
    const int NV = 32 * KW;    // float4 elements per tile

    {
        const float4* W4 = (const float4*)W;
        float4* Ws4 = (float4*)Ws;
        for (int i = t; i < K * 25; i += 128) Ws4[i] = W4[i];
    }

    float4 av = make_float4(0.f, 0.f, 0.f, 0.f);
    if (lane < 25) av = ((const float4*)avec)[lane];

    const float4* X4 = (const float4*)X;
    const int stride = gridDim.x * 32;

    float4 buf[8];
    // prologue: load first tile into registers
    {
        int g0 = blockIdx.x * 32;
        if (g0 < N) {
#pragma unroll
            for (int j = 0; j < 8; j++) {
                int i = t + j * 128;
                if (i < NV) {
                    int r = i / KW, c = i - r * KW;
                    float4 v = make_float4(0.f, 0.f, 0.f, 0.f);
                    if (g0 + r < N) v = X4[(size_t)(g0 + r) * KW + c];
                    buf[j] = v;
                }
            }
        }
    }

    for (int g0 = blockIdx.x * 32; g0 < N; g0 += stride) {
        __syncthreads();   // previous compute done; xs free
        {
            float4* xs4 = (float4*)xs;
#pragma unroll
            for (int j = 0; j < 8; j++) {
                int i = t + j * 128;
                if (i < NV) {
                    float4 v = buf[j];
                    if (ELU) {
                        v.x = elu_f(v.x); v.y = elu_f(v.y);
                        v.z = elu_f(v.z); v.w = elu_f(v.w);
                    }
                    xs4[i] = v;
                }
            }
        }
        __syncthreads();
        // prefetch next tile (overlaps the compute below)
        {
            int gn = g0 + stride;
            if (gn < N) {
#pragma unroll
                for (int j = 0; j < 8; j++) {
                    int i = t + j * 128;
                    if (i < NV) {
                        int r = i / KW, c = i - r * KW;
                        float4 v = make_float4(0.f, 0.f, 0.f, 0.f);
                        if (gn + r < N) v = X4[(size_t)(gn + r) * KW + c];
                        buf[j] = v;
                    }
                }
            }
        }

        float acc[8][4];
#pragma unroll
        for (int r = 0; r < 8; r++)
#pragma unroll
            for (int j = 0; j < 4; j++) acc[r][j] = 0.f;

        if (lane < 25) {
            const float4* Ws4 = (const float4*)Ws;
            const float4* xr = (const float4*)(xs + w * 8 * K);
#pragma unroll 2
            for (int k4 = 0; k4 < KW; k4++) {
                float4 w0 = Ws4[(4 * k4 + 0) * 25 + lane];
                float4 w1 = Ws4[(4 * k4 + 1) * 25 + lane];
                float4 w2 = Ws4[(4 * k4 + 2) * 25 + lane];
                float4 w3 = Ws4[(4 * k4 + 3) * 25 + lane];
#pragma unroll
                for (int r = 0; r < 8; r++) {
                    float4 xv = xr[r * KW + k4];
                    acc[r][0] += xv.x * w0.x; acc[r][1] += xv.x * w0.y;
                    acc[r][2] += xv.x * w0.z; acc[r][3] += xv.x * w0.w;
                    acc[r][0] += xv.y * w1.x; acc[r][1] += xv.y * w1.y;
                    acc[r][2] += xv.y * w1.z; acc[r][3] += xv.y * w1.w;
                    acc[r][0] += xv.z * w2.x; acc[r][1] += xv.z * w2.y;
                    acc[r][2] += xv.z * w2.z; acc[r][3] += xv.z * w2.w;
                    acc[r][0] += xv.w * w3.x; acc[r][1] += xv.w * w3.y;
                    acc[r][2] += xv.w * w3.z; acc[r][3] += xv.w * w3.w;
                }
            }
        }

#pragma unroll
        for (int r = 0; r < 8; r++) {
            int n = g0 + w * 8 + r;
            bool ok = (n < N);
            if (ok && lane < 25) {
                float4 hv = make_float4(acc[r][0], acc[r][1], acc[r][2], acc[r][3]);
                ((float4*)(H + (size_t)n * 100))[lane] = hv;
            }
            if (HEADS == 1) {
                float s = acc[r][0] * av.x + acc[r][1] * av.y +
                          acc[r][2] * av.z + acc[r][3] * av.w;
#pragma unroll
                for (int o = 16; o > 0; o >>= 1)
                    s += __shfl_xor_sync(0xffffffffu, s, o);
                if (ok && lane == 0) att[n] = s;
            } else {
                float s0 = 0.f, s1 = 0.f, s2 = 0.f, s3 = 0.f;
#pragma unroll
                for (int j = 0; j < 4; j++) {
                    int c = 4 * lane + j;
                    float a = (j == 0) ? av.x : (j == 1) ? av.y
                              : (j == 2) ? av.z : av.w;
                    float v = acc[r][j] * a;
                    int h = c / 25;
                    if (h == 0) s0 += v;
                    else if (h == 1) s1 += v;
                    else if (h == 2) s2 += v;
                    else s3 += v;
                }
#pragma unroll
                for (int o = 16; o > 0; o >>= 1) {
                    s0 += __shfl_xor_sync(0xffffffffu, s0, o);
                    s1 += __shfl_xor_sync(0xffffffffu, s1, o);
                    s2 += __shfl_xor_sync(0xffffffffu, s2, o);
                    s3 += __shfl_xor_sync(0xffffffffu, s3, o);
                }
                if (ok && lane == 0) {
                    float* ap = att + (size_t)n * 4;
                    ap[0] = s0; ap[1] = s1; ap[2] = s2; ap[3] = s3;
                }
            }
        }
    }
}

// ---------------------------------------------------------------------------
// GEMV: att[n,h] = sum_k X[n,k] * wv[k,h].  Warp per node.  (round-14 form)
// ---------------------------------------------------------------------------
__global__ __launch_bounds__(256)
void k_gemv4(const float* __restrict__ X, const float4* __restrict__ wv,
             float* __restrict__ att, int N) {
    int lane = threadIdx.x & 31;
    int n = (blockIdx.x * blockDim.x + threadIdx.x) >> 5;
    float4 w0 = wv[4 * lane + 0];
    float4 w1 = wv[4 * lane + 1];
    float4 w2 = wv[4 * lane + 2];
    float4 w3 = wv[4 * lane + 3];
    if (n >= N) return;
    float4 xv = ((const float4*)X)[(size_t)n * 32 + lane];
    float s0 = xv.x * w0.x + xv.y * w1.x + xv.z * w2.x + xv.w * w3.x;
    float s1 = xv.x * w0.y + xv.y * w1.y + xv.z * w2.y + xv.w * w3.y;
    float s2 = xv.x * w0.z + xv.y * w1.z + xv.z * w2.z + xv.w * w3.z;
    float s3 = xv.x * w0.w + xv.y * w1.w + xv.z * w2.w + xv.w * w3.w;
#pragma unroll
    for (int o = 16; o > 0; o >>= 1) {
        s0 += __shfl_xor_sync(0xffffffffu, s0, o);
        s1 += __shfl_xor_sync(0xffffffffu, s1, o);
        s2 += __shfl_xor_sync(0xffffffffu, s2, o);
        s3 += __shfl_xor_sync(0xffffffffu, s3, o);
    }
    if (lane == 0) ((float4*)att)[n] = make_float4(s0, s1, s2, s3);
}

__global__ __launch_bounds__(256)
void k_gemv1(const float* __restrict__ X, const float* __restrict__ wv,
             float* __restrict__ att, int N) {
    int lane = threadIdx.x & 31;
    int n = (blockIdx.x * blockDim.x + threadIdx.x) >> 5;
    float4 wvv = make_float4(0.f, 0.f, 0.f, 0.f);
    if (lane < 25) wvv = ((const float4*)wv)[lane];
    if (n >= N) return;
    float s = 0.f;
    if (lane < 25) {
        float4 xv = ((const float4*)X)[(size_t)n * 25 + lane];
        s = elu_f(xv.x) * wvv.x + elu_f(xv.y) * wvv.y +
            elu_f(xv.z) * wvv.z + elu_f(xv.w) * wvv.w;
    }
#pragma unroll
    for (int o = 16; o > 0; o >>= 1) s += __shfl_xor_sync(0xffffffffu, s, o);
    if (lane == 0) att[n] = s;
}

// ---------------------------------------------------------------------------
// Fused GAT gather: one warp per destination node (round-14 form, no prefetch).
// rowptr may be offset (rowptr+NN) for the second direction; srcs/ews are the
// concatenated dst-sorted arrays indexed absolutely.
// ---------------------------------------------------------------------------
template <int HEADS>
__global__ __launch_bounds__(256)
void k_gat(const int* __restrict__ rowptr, const int* __restrict__ srcs,
           const float* __restrict__ ews, const float* __restrict__ ce,
           const float* __restrict__ atts, const float* __restrict__ attd,
           const float* __restrict__ hs, const float* __restrict__ bias,
           float* __restrict__ out, int n) {
    int wid = (blockIdx.x * blockDim.x + threadIdx.x) >> 5;
    int lane = threadIdx.x & 31;
    if (wid >= n) return;
    int beg = rowptr[wid], end = rowptr[wid + 1];
    const float4* hs4 = (const float4*)hs;
    const float4* b4 = (const float4*)bias;
    if (end == beg) {
        if (lane < 25) ((float4*)out)[(size_t)wid * 25 + lane] = b4[lane];
        return;
    }
    float4 acc = make_float4(0.f, 0.f, 0.f, 0.f);
    if (HEADS == 4) {
        int c0 = 4 * lane;
        int h0 = c0 / 25, h1 = (c0 + 1) / 25, h2 = (c0 + 2) / 25, h3 = (c0 + 3) / 25;
        float ad_l = 0.f, ce_l = 0.f;
        if (lane < 4) {
            ad_l = attd[(size_t)wid * 4 + lane];
            ce_l = ce[lane];
        }
        float dn = 0.f;
        for (int i = beg; i < end; i++) {
            int s = srcs[i];
            float wv = ews[i];
            float v = 0.f;
            if (lane < 4) {
                float l = atts[(size_t)s * 4 + lane] + ad_l + wv * ce_l;
                l = (l > 0.f) ? l : 0.2f * l;
                v = __expf(l);
                dn += v;
            }
            float a0 = __shfl_sync(0xffffffffu, v, h0);
            float a1 = __shfl_sync(0xffffffffu, v, h1);
            float a2 = __shfl_sync(0xffffffffu, v, h2);
            float a3 = __shfl_sync(0xffffffffu, v, h3);
            if (lane < 25) {
                float4 hv = hs4[(size_t)s * 25 + lane];
                acc.x += a0 * hv.x; acc.y += a1 * hv.y;
                acc.z += a2 * hv.z; acc.w += a3 * hv.w;
            }
        }
        float r0 = __shfl_sync(0xffffffffu, dn, h0);
        float r1 = __shfl_sync(0xffffffffu, dn, h1);
        float r2 = __shfl_sync(0xffffffffu, dn, h2);
        float r3 = __shfl_sync(0xffffffffu, dn, h3);
        if (lane < 25) {
            float4 bv = b4[lane];
            float4 o;
            o.x = bv.x + __fdividef(acc.x, r0);
            o.y = bv.y + __fdividef(acc.y, r1);
            o.z = bv.z + __fdividef(acc.z, r2);
            o.w = bv.w + __fdividef(acc.w, r3);
            ((float4*)out)[(size_t)wid * 25 + lane] = o;
        }
    } else {
        float ad = attd[wid];
        float dn = 0.f;
        for (int i = beg; i < end; i++) {
            int s = srcs[i];
            float v = 0.f;
            if (lane == 0) {
                float l = atts[s] + ad;
                l = (l > 0.f) ? l : 0.2f * l;
                v = __expf(l);
                dn += v;
            }
            float a = __shfl_sync(0xffffffffu, v, 0);
            if (lane < 25) {
                float4 hv = hs4[(size_t)s * 25 + lane];
                acc.x += a * hv.x; acc.y += a * hv.y;
                acc.z += a * hv.z; acc.w += a * hv.w;
            }
        }
        float r = __shfl_sync(0xffffffffu, dn, 0);
        if (lane < 25) {
            float4 bv = b4[lane];
            float rr = __fdividef(1.f, r);
            float4 o;
            o.x = bv.x + acc.x * rr; o.y = bv.y + acc.y * rr;
            o.z = bv.z + acc.z * rr; o.w = bv.w + acc.w * rr;
            ((float4*)out)[(size_t)wid * 25 + lane] = o;
        }
    }
}

// ---------------------------------------------------------------------------
// Host orchestration
// ---------------------------------------------------------------------------
extern "C" void kernel_launch(void* const* d_in, const int* in_sizes, int n_in,
                              void* d_out, int out_size) {
    (void)in_sizes; (void)n_in; (void)out_size;

    const float* x_A  = (const float*)d_in[0];
    const float* x_B  = (const float*)d_in[1];
    const int*   eiAB = (const int*)d_in[2];
    const int*   eiBA = (const int*)d_in[3];
    const float* w_AB = (const float*)d_in[4];
    const float* w_BA = (const float*)d_in[5];
    const float* l1ABWs = (const float*)d_in[6];
    const float* l1ABWd = (const float*)d_in[7];
    const float* l1ABas = (const float*)d_in[8];
    const float* l1ABad = (const float*)d_in[9];
    const float* l1ABWe = (const float*)d_in[10];
    const float* l1ABae = (const float*)d_in[11];
    const float* l1ABb  = (const float*)d_in[12];
    const float* l2ABWs = (const float*)d_in[13];
    const float* l2ABWd = (const float*)d_in[14];
    const float* l2ABas = (const float*)d_in[15];
    const float* l2ABad = (const float*)d_in[16];
    const float* l2ABb  = (const float*)d_in[17];
    const float* l1BAWs = (const float*)d_in[18];
    const float* l1BAWd = (const float*)d_in[19];
    const float* l1BAas = (const float*)d_in[20];
    const float* l1BAad = (const float*)d_in[21];
    const float* l1BAWe = (const float*)d_in[22];
    const float* l1BAae = (const float*)d_in[23];
    const float* l1BAb  = (const float*)d_in[24];
    const float* l2BAWs = (const float*)d_in[25];
    const float* l2BAWd = (const float*)d_in[26];
    const float* l2BAas = (const float*)d_in[27];
    const float* l2BAad = (const float*)d_in[28];
    const float* l2BAb  = (const float*)d_in[29];

    const int* sAB = eiAB;        const int* dAB = eiAB + EE;
    const int* sBA = eiBA;        const int* dBA = eiBA + EE;

    void* sp = nullptr;
    cudaGetSymbolAddress(&sp, g_scratch);
    float* p = (float*)sp;
    float* hsA  = p; p += (size_t)NN * HID;   // x_A @ l1_AB_Ws
    float* hsB  = p; p += (size_t)NN * HID;   // x_B @ l1_BA_Ws
    float* hA   = p; p += (size_t)NN * HID;   // layer-1 output A (incl bias)
    float* hB   = p; p += (size_t)NN * HID;   // layer-1 output B (incl bias)
    float* hs2A = p; p += (size_t)NN * HID;   // elu(hA) @ l2_AB_Ws
    float* hs2B = p; p += (size_t)NN * HID;   // elu(hB) @ l2_BA_Ws
    float* asAB = p; p += (size_t)NN * 4;
    float* adAB = p; p += (size_t)NN * 4;
    float* asBA = p; p += (size_t)NN * 4;
    float* adBA = p; p += (size_t)NN * 4;
    float* ce   = p; p += 16;
    float* wv1AB = p; p += 512;
    float* wv1BA = p; p += 512;
    float* wv2AB = p; p += 128;
    float* wv2BA = p; p += 128;
    p += 752;                                  // pad
    float* ew_s = p; p += 2ull * EE;           // dst-sorted edge weights (both)
    int* ip = (int*)p;
    int* rowptr = ip; ip += 2 * NN + 1;
    int* cursor = ip; ip += 2 * NN;
    ip += 3;                                   // align
    int* src_s = ip; ip += 2 * EE;             // dst-sorted src ids (both)

    float* oA = (float*)d_out;
    float* oB = oA + (size_t)NN * HID;

    cudaFuncSetAttribute((const void*)k_gemm_att<128, 4, false>,
                         cudaFuncAttributeMaxDynamicSharedMemorySize, 69632);
    cudaFuncSetAttribute((const void*)k_gemm_att<100, 1, true>,
                         cudaFuncAttributeMaxDynamicSharedMemorySize, 61440);

    const int GRID_GEMM = 444;
    const size_t SM128 = (128 * 100 + 32 * 128) * sizeof(float);   // 67.5 KB
    const size_t SM100 = (100 * 100 + 32 * 100) * sizeof(float);   // 52.8 KB
    const int EB2 = (2 * EE + 255) / 256;
    const int NB2 = (2 * NN + 255) / 256;
    const int GAT_BLOCKS = (NN * 32 + 255) / 256;    // warp per node, one dir
    const int GEMV_BLOCKS = (NN * 32 + 255) / 256;

    // ---------------- CSR build (once; both directions) ------------------
    k_zero_int<<<NB2, 256>>>(cursor, 2 * NN);
    k_hist2<<<EB2, 256>>>(dAB, dBA, cursor);
    k_scan<<<1, 1024>>>(cursor, rowptr, cursor, 2 * NN);
    k_scatter2<<<EB2, 256>>>(sAB, dAB, w_AB, sBA, dBA, w_BA, cursor, src_s, ew_s);

    k_ce2<<<2, 32>>>(l1ABWe, l1ABae, l1BAWe, l1BAae, ce);
    k_wv4_2<<<2, 128>>>(l1ABWd, l1ABad, (float4*)wv1AB,
                        l1BAWd, l1BAad, (float4*)wv1BA, 128);

    // ---------------- Layer 1 (heads=4, edge term) -----------------------
    k_gemm_att<128, 4, false><<<GRID_GEMM, 128, SM128>>>(x_A, l1ABWs, l1ABas, hsA, asAB, NN);
    k_gemm_att<128, 4, false><<<GRID_GEMM, 128, SM128>>>(x_B, l1BAWs, l1BAas, hsB, asBA, NN);
    k_gemv4<<<GEMV_BLOCKS, 256>>>(x_B, (const float4*)wv1AB, adAB, NN);
    k_gemv4<<<GEMV_BLOCKS, 256>>>(x_A, (const float4*)wv1BA, adBA, NN);

    k_gat<4><<<GAT_BLOCKS, 256>>>(rowptr,      src_s, ew_s, ce,     asAB, adAB, hsA, l1ABb, hB, NN);
    k_gat<4><<<GAT_BLOCKS, 256>>>(rowptr + NN, src_s, ew_s, ce + 4, asBA, adBA, hsB, l1BAb, hA, NN);

    // ---------------- Layer 2 (heads=1, ELU fused) -----------------------
    k_wv1_2<<<2, 128>>>(l2ABWd, l2ABad, wv2AB, l2BAWd, l2BAad, wv2BA, 100);

    k_gemm_att<100, 1, true><<<GRID_GEMM, 128, SM100>>>(hA, l2ABWs, l2ABas, hs2A, asAB, NN);
    k_gemm_att<100, 1, true><<<GRID_GEMM, 128, SM100>>>(hB, l2BAWs, l2BAas, hs2B, asBA, NN);
    k_gemv1<<<GEMV_BLOCKS, 256>>>(hB, wv2AB, adAB, NN);
    k_gemv1<<<GEMV_BLOCKS, 256>>>(hA, wv2BA, adBA, NN);

    k_gat<1><<<GAT_BLOCKS, 256>>>(rowptr,      src_s, nullptr, nullptr, asAB, adAB, hs2A, l2ABb, oB, NN);
    k_gat<1><<<GAT_BLOCKS, 256>>>(rowptr + NN, src_s, nullptr, nullptr, asBA, adBA, hs2B, l2BAb, oA, NN);
}